// round 3
// baseline (speedup 1.0000x reference)
#include <cuda_runtime.h>
#include <float.h>
#include <math.h>

// Problem constants (fixed by the reference: x is [8192, 128] fp32, n_images=2)
#define N_TOT   8192
#define DIM     128
#define P_CNT   4096          // N_TOT / n_images
#define TILE    64
#define NT      (N_TOT / TILE)            // 128 row/col tiles
#define NBLOCKS (NT * (NT + 1) / 2)       // 8256 upper-triangular tiles (incl. diagonal)

// Per-block top-2 scratch (device globals: allocation-free)
__device__ float g_v1[NBLOCKS];
__device__ float g_v2[NBLOCKS];
__device__ int   g_i1[NBLOCKS];

// ---------------------------------------------------------------------------
// Kernel 1: for one 64x64 tile of G = x x^T (upper-triangular tile set),
// compute the tile with register blocking and reduce its strict-upper-triangle
// entries to a per-block (top1 value, top1 flat index, top2 value).
// ---------------------------------------------------------------------------
__global__ void __launch_bounds__(256, 2)
top2_tile_kernel(const float* __restrict__ x)
{
    // Dynamic SMEM: As[k][r] and Bs[k][c], both [128][64] fp32 (32 KB each)
    extern __shared__ float smem_dyn[];
    float* As = smem_dyn;               // 128*64
    float* Bs = smem_dyn + DIM * TILE;  // 128*64

    // Map blockIdx.x -> (ti, tj) with ti <= tj
    int b = blockIdx.x;
    int ti = 0;
    {
        int rem = b;
        while (rem >= NT - ti) { rem -= NT - ti; ti++; }
        b = rem;
    }
    int tj = ti + b;

    const int tid = threadIdx.x;
    const int rowbase = ti * TILE;
    const int colbase = tj * TILE;

    // Load A and B tiles transposed into SMEM: As[k][r] = x[rowbase+r][k].
    // 64 rows x 32 float4 chunks = 2048 float4 per tile; 256 threads, 8 iters.
    #pragma unroll
    for (int it = 0; it < 8; it++) {
        int idx = tid + it * 256;
        int r   = idx & 63;
        int kc  = idx >> 6;          // 0..31 (float4 chunk along K)
        float4 va = *(const float4*)(x + (size_t)(rowbase + r) * DIM + kc * 4);
        As[(kc * 4 + 0) * TILE + r] = va.x;
        As[(kc * 4 + 1) * TILE + r] = va.y;
        As[(kc * 4 + 2) * TILE + r] = va.z;
        As[(kc * 4 + 3) * TILE + r] = va.w;
        float4 vb = *(const float4*)(x + (size_t)(colbase + r) * DIM + kc * 4);
        Bs[(kc * 4 + 0) * TILE + r] = vb.x;
        Bs[(kc * 4 + 1) * TILE + r] = vb.y;
        Bs[(kc * 4 + 2) * TILE + r] = vb.z;
        Bs[(kc * 4 + 3) * TILE + r] = vb.w;
    }
    __syncthreads();

    // 16x16 thread grid, each thread owns a 4x4 micro-tile.
    const int tx = tid & 15;
    const int ty = tid >> 4;

    float acc[4][4] = {};
    #pragma unroll 8
    for (int k = 0; k < DIM; k++) {
        float4 a4 = *(const float4*)(As + k * TILE + ty * 4);
        float4 b4 = *(const float4*)(Bs + k * TILE + tx * 4);
        float av[4] = { a4.x, a4.y, a4.z, a4.w };
        float bv[4] = { b4.x, b4.y, b4.z, b4.w };
        #pragma unroll
        for (int u = 0; u < 4; u++)
            #pragma unroll
            for (int v = 0; v < 4; v++)
                acc[u][v] = fmaf(av[u], bv[v], acc[u][v]);
    }

    // Per-thread top-2 over valid (j > i) entries of the micro-tile.
    float v1 = -FLT_MAX, v2 = -FLT_MAX;
    int   i1 = -1;
    #pragma unroll
    for (int u = 0; u < 4; u++) {
        int gi = rowbase + ty * 4 + u;
        #pragma unroll
        for (int v = 0; v < 4; v++) {
            int gj = colbase + tx * 4 + v;
            if (gj > gi) {
                float val = acc[u][v];
                if (val > v1) { v2 = v1; v1 = val; i1 = gi * N_TOT + gj; }
                else if (val > v2) { v2 = val; }
            }
        }
    }

    // Block reduction (reuse As region — everyone is done reading SMEM).
    __syncthreads();
    float* rv1 = As;
    float* rv2 = As + 256;
    int*   ri1 = (int*)(As + 512);
    rv1[tid] = v1; rv2[tid] = v2; ri1[tid] = i1;
    __syncthreads();
    #pragma unroll
    for (int s = 128; s > 0; s >>= 1) {
        if (tid < s) {
            float bv1 = rv1[tid + s], bv2 = rv2[tid + s];
            int   bi1 = ri1[tid + s];
            if (bv1 > rv1[tid]) {
                rv2[tid] = fmaxf(rv1[tid], bv2);
                rv1[tid] = bv1;
                ri1[tid] = bi1;
            } else {
                rv2[tid] = fmaxf(rv2[tid], bv1);
            }
        }
        __syncthreads();
    }
    if (tid == 0) {
        g_v1[blockIdx.x] = rv1[0];
        g_v2[blockIdx.x] = rv2[0];
        g_i1[blockIdx.x] = ri1[0];
    }
}

// ---------------------------------------------------------------------------
// Kernel 2 (single block): merge per-block top-2 -> global (V1, I1, V2),
// compute sim_self[p] = dot(x[p], x[p+1]) for p in [0, 4096), and the mean
// of sim_oth/sim_self.
// ---------------------------------------------------------------------------
__global__ void __launch_bounds__(256)
finalize_kernel(const float* __restrict__ x, float* __restrict__ out)
{
    __shared__ float  sv1[256];
    __shared__ float  sv2[256];
    __shared__ int    si1[256];
    __shared__ double ssum[256];

    const int tid = threadIdx.x;

    // Merge block results.
    float v1 = -FLT_MAX, v2 = -FLT_MAX;
    int   i1 = -1;
    for (int b = tid; b < NBLOCKS; b += 256) {
        float bv1 = g_v1[b], bv2 = g_v2[b];
        int   bi1 = g_i1[b];
        if (bv1 > v1) { v2 = fmaxf(v1, bv2); v1 = bv1; i1 = bi1; }
        else          { v2 = fmaxf(v2, bv1); }
    }
    sv1[tid] = v1; sv2[tid] = v2; si1[tid] = i1;
    __syncthreads();
    #pragma unroll
    for (int s = 128; s > 0; s >>= 1) {
        if (tid < s) {
            float bv1 = sv1[tid + s], bv2 = sv2[tid + s];
            int   bi1 = si1[tid + s];
            if (bv1 > sv1[tid]) {
                sv2[tid] = fmaxf(sv1[tid], bv2);
                sv1[tid] = bv1;
                si1[tid] = bi1;
            } else {
                sv2[tid] = fmaxf(sv2[tid], bv1);
            }
        }
        __syncthreads();
    }
    const float V1 = sv1[0];
    const float V2 = sv2[0];
    const int   I1 = si1[0];

    // sim_self dots + ratio sum.
    double sum = 0.0;
    for (int p = tid; p < P_CNT; p += 256) {
        const float4* xa = (const float4*)(x + (size_t)p * DIM);
        const float4* xb = (const float4*)(x + (size_t)(p + 1) * DIM);
        float a0 = 0.f, a1 = 0.f, a2 = 0.f, a3 = 0.f;
        #pragma unroll
        for (int c = 0; c < DIM / 4; c++) {
            float4 a = xa[c];
            float4 b = xb[c];
            a0 = fmaf(a.x, b.x, a0);
            a1 = fmaf(a.y, b.y, a1);
            a2 = fmaf(a.z, b.z, a2);
            a3 = fmaf(a.w, b.w, a3);
        }
        float s_self = (a0 + a1) + (a2 + a3);
        float oth = (I1 == p * N_TOT + (p + 1)) ? V2 : V1;
        sum += (double)(oth / s_self);
    }
    ssum[tid] = sum;
    __syncthreads();
    #pragma unroll
    for (int s = 128; s > 0; s >>= 1) {
        if (tid < s) ssum[tid] += ssum[tid + s];
        __syncthreads();
    }
    if (tid == 0) out[0] = (float)(ssum[0] / (double)P_CNT);
}

// ---------------------------------------------------------------------------
extern "C" void kernel_launch(void* const* d_in, const int* in_sizes, int n_in,
                              void* d_out, int out_size)
{
    const float* x  = (const float*)d_in[0];
    float* out      = (float*)d_out;

    const int smem_bytes = 2 * DIM * TILE * (int)sizeof(float);  // 64 KB
    cudaFuncSetAttribute(top2_tile_kernel,
                         cudaFuncAttributeMaxDynamicSharedMemorySize, smem_bytes);

    top2_tile_kernel<<<NBLOCKS, 256, smem_bytes>>>(x);
    finalize_kernel<<<1, 256>>>(x, out);
}

// round 11
// speedup vs baseline: 1.6233x; 1.6233x over previous
#include <cuda_runtime.h>
#include <float.h>
#include <math.h>
#include <cstdint>

// ---------------------------------------------------------------------------
// Problem constants: x is [8192, 128] fp32, n_images = 2.
// ---------------------------------------------------------------------------
#define N_TOT   8192
#define DIM     128
#define P_CNT   4096
#define TILE2   128
#define NT2     (N_TOT / TILE2)             // 64
#define NBLK2   (NT2 * (NT2 + 1) / 2)       // 2080 upper-tri 128x128 tiles
#define NCAND   8

// ---------------------------------------------------------------------------
// Device scratch (allocation-free)
// ---------------------------------------------------------------------------
__device__ float  g_bv1[NBLK2];
__device__ int    g_bi1[NBLK2];
__device__ float  g_bv2[NBLK2];
__device__ int    g_bi2[NBLK2];
__device__ float  g_V1f, g_V2f;
__device__ int    g_I1;
__device__ double g_part[16];

// Round-0-style fp32 dot: float4 lanes, 4 fmaf accumulators, (a0+a1)+(a2+a3).
__device__ __forceinline__ float dot_fp32_r0(const float* __restrict__ x, int gi, int gj)
{
    const float4* xa = (const float4*)(x + (size_t)gi * DIM);
    const float4* xb = (const float4*)(x + (size_t)gj * DIM);
    float a0 = 0.f, a1 = 0.f, a2 = 0.f, a3 = 0.f;
    #pragma unroll
    for (int c = 0; c < DIM / 4; c++) {
        float4 a = xa[c];
        float4 b = xb[c];
        a0 = fmaf(a.x, b.x, a0);
        a1 = fmaf(a.y, b.y, a1);
        a2 = fmaf(a.z, b.z, a2);
        a3 = fmaf(a.w, b.w, a3);
    }
    return (a0 + a1) + (a2 + a3);
}

// ---------------------------------------------------------------------------
// Kernel 1: EXACT fp32 128x128 Gram tile, 8x8 register blocking (FMA-bound),
// + per-block top-2 (value, flat index).
// SMEM: As[k][r], Bs[k][c] both [128][128] fp32 = 64 KB each (128 KB total).
// ---------------------------------------------------------------------------
__global__ void __launch_bounds__(256, 1)
gram_exact_kernel(const float* __restrict__ x)
{
    extern __shared__ float sm[];
    float* As = sm;                  // 128*128
    float* Bs = sm + TILE2 * TILE2;  // 128*128

    const int tid = threadIdx.x;

    // blockIdx -> (ti, tj), ti <= tj
    int b = blockIdx.x;
    int ti = 0;
    while (b >= NT2 - ti) { b -= NT2 - ti; ti++; }
    const int tj = ti + b;
    const int rowbase = ti * TILE2;
    const int colbase = tj * TILE2;

    // Load both tiles transposed: As[k][r] = x[rowbase+r][k].
    // 128 rows x 32 float4 chunks = 4096 float4 per tile; 256 threads x 16 it.
    // Lanes take consecutive r at fixed chunk -> conflict-free STS.
    #pragma unroll
    for (int it = 0; it < 16; it++) {
        int idx = tid + it * 256;
        int r     = idx & 127;
        int chunk = idx >> 7;        // 0..31
        float4 va = *(const float4*)(x + (size_t)(rowbase + r) * DIM + chunk * 4);
        As[(chunk * 4 + 0) * TILE2 + r] = va.x;
        As[(chunk * 4 + 1) * TILE2 + r] = va.y;
        As[(chunk * 4 + 2) * TILE2 + r] = va.z;
        As[(chunk * 4 + 3) * TILE2 + r] = va.w;
        float4 vb = *(const float4*)(x + (size_t)(colbase + r) * DIM + chunk * 4);
        Bs[(chunk * 4 + 0) * TILE2 + r] = vb.x;
        Bs[(chunk * 4 + 1) * TILE2 + r] = vb.y;
        Bs[(chunk * 4 + 2) * TILE2 + r] = vb.z;
        Bs[(chunk * 4 + 3) * TILE2 + r] = vb.w;
    }
    __syncthreads();

    // 16x16 threads, each owns an 8x8 micro-tile.
    const int tx = tid & 15;
    const int ty = tid >> 4;
    const int my_r = ty * 8;
    const int my_c = tx * 8;

    float acc[8][8];
    #pragma unroll
    for (int u = 0; u < 8; u++)
        #pragma unroll
        for (int v = 0; v < 8; v++) acc[u][v] = 0.f;

    #pragma unroll 4
    for (int k = 0; k < DIM; k++) {
        float4 a0 = *(const float4*)(As + k * TILE2 + my_r);
        float4 a1 = *(const float4*)(As + k * TILE2 + my_r + 4);
        float4 b0 = *(const float4*)(Bs + k * TILE2 + my_c);
        float4 b1 = *(const float4*)(Bs + k * TILE2 + my_c + 4);
        float av[8] = { a0.x, a0.y, a0.z, a0.w, a1.x, a1.y, a1.z, a1.w };
        float bv[8] = { b0.x, b0.y, b0.z, b0.w, b1.x, b1.y, b1.z, b1.w };
        #pragma unroll
        for (int u = 0; u < 8; u++)
            #pragma unroll
            for (int v = 0; v < 8; v++)
                acc[u][v] = fmaf(av[u], bv[v], acc[u][v]);
    }

    // Per-thread top-2 over valid (j > i) entries.
    float v1 = -FLT_MAX, v2 = -FLT_MAX;
    int   i1 = -1,       i2 = -1;
    #pragma unroll
    for (int u = 0; u < 8; u++) {
        int grow = rowbase + my_r + u;
        #pragma unroll
        for (int v = 0; v < 8; v++) {
            int gcol = colbase + my_c + v;
            if (gcol > grow) {
                float val = acc[u][v];
                if (val > v1) { v2 = v1; i2 = i1; v1 = val; i1 = grow * N_TOT + gcol; }
                else if (val > v2) { v2 = val; i2 = grow * N_TOT + gcol; }
            }
        }
    }

    // Block reduce (v1,i1,v2,i2); reuse tile SMEM.
    __syncthreads();
    float* rv1 = As;
    float* rv2 = As + 256;
    int*   ri1 = (int*)(As + 512);
    int*   ri2 = (int*)(As + 768);
    rv1[tid] = v1; rv2[tid] = v2; ri1[tid] = i1; ri2[tid] = i2;
    __syncthreads();
    #pragma unroll
    for (int s = 128; s > 0; s >>= 1) {
        if (tid < s) {
            float av1 = rv1[tid], av2 = rv2[tid];
            int   ai1 = ri1[tid];
            float bv1 = rv1[tid + s], bv2 = rv2[tid + s];
            int   bi1 = ri1[tid + s], bi2 = ri2[tid + s];
            if (bv1 > av1) {
                rv1[tid] = bv1; ri1[tid] = bi1;
                if (av1 > bv2) { rv2[tid] = av1; ri2[tid] = ai1; }
                else           { rv2[tid] = bv2; ri2[tid] = bi2; }
            } else {
                if (bv1 > av2) { rv2[tid] = bv1; ri2[tid] = bi1; }
            }
        }
        __syncthreads();
    }
    if (tid == 0) {
        g_bv1[blockIdx.x] = rv1[0]; g_bi1[blockIdx.x] = ri1[0];
        g_bv2[blockIdx.x] = rv2[0]; g_bi2[blockIdx.x] = ri2[0];
    }
}

// ---------------------------------------------------------------------------
// Kernel 2: merge per-block candidates -> top-NCAND, recompute those pair-dots
// with round-0 fp32 ordering, select top-2 -> g_V1f/g_V2f/g_I1.
// (Same machinery as rounds 6-9 — this run adjudicates it.)
// ---------------------------------------------------------------------------
__global__ void __launch_bounds__(256)
candidate_kernel(const float* __restrict__ x)
{
    __shared__ float cv[1024];
    __shared__ int   ci[1024];
    __shared__ float cv2[128];
    __shared__ int   ci2[128];
    __shared__ float ev[NCAND];
    __shared__ int   eidx[NCAND];

    const int tid = threadIdx.x;

    // Stage 1: per-thread top-4 over 2*NBLK2 entries.
    float lv[4] = { -FLT_MAX, -FLT_MAX, -FLT_MAX, -FLT_MAX };
    int   li[4] = { -1, -1, -1, -1 };
    for (int e = tid; e < 2 * NBLK2; e += 256) {
        int bb = e >> 1;
        float v = (e & 1) ? g_bv2[bb] : g_bv1[bb];
        int   i = (e & 1) ? g_bi2[bb] : g_bi1[bb];
        if (v > lv[3]) {
            int q = 3;
            while (q > 0 && v > lv[q - 1]) { lv[q] = lv[q - 1]; li[q] = li[q - 1]; q--; }
            lv[q] = v; li[q] = i;
        }
    }
    #pragma unroll
    for (int q = 0; q < 4; q++) { cv[tid * 4 + q] = lv[q]; ci[tid * 4 + q] = li[q]; }
    __syncthreads();

    // Stage 2: 32 threads each merge 8 lists -> top-4 into cv2/ci2.
    if (tid < 32) {
        float mv[4] = { -FLT_MAX, -FLT_MAX, -FLT_MAX, -FLT_MAX };
        int   mi[4] = { -1, -1, -1, -1 };
        for (int e = 0; e < 32; e++) {
            float v = cv[tid * 32 + e];
            int   i = ci[tid * 32 + e];
            if (v > mv[3]) {
                int q = 3;
                while (q > 0 && v > mv[q - 1]) { mv[q] = mv[q - 1]; mi[q] = mi[q - 1]; q--; }
                mv[q] = v; mi[q] = i;
            }
        }
        #pragma unroll
        for (int q = 0; q < 4; q++) { cv2[tid * 4 + q] = mv[q]; ci2[tid * 4 + q] = mi[q]; }
    }
    __syncthreads();

    // Stage 3: thread 0 merges 128 entries -> final top-NCAND candidates.
    if (tid == 0) {
        float fv[NCAND];
        int   fi[NCAND];
        #pragma unroll
        for (int q = 0; q < NCAND; q++) { fv[q] = -FLT_MAX; fi[q] = -1; }
        for (int e = 0; e < 128; e++) {
            float v = cv2[e];
            int   i = ci2[e];
            if (v > fv[NCAND - 1]) {
                int q = NCAND - 1;
                while (q > 0 && v > fv[q - 1]) { fv[q] = fv[q - 1]; fi[q] = fi[q - 1]; q--; }
                fv[q] = v; fi[q] = i;
            }
        }
        #pragma unroll
        for (int q = 0; q < NCAND; q++) eidx[q] = fi[q];
    }
    __syncthreads();

    // Recompute candidate pair-dots with round-0 fp32 ordering.
    if (tid < NCAND) {
        int idx = eidx[tid];
        float s = -FLT_MAX;
        if (idx >= 0) {
            int gi = idx / N_TOT, gj = idx % N_TOT;
            s = dot_fp32_r0(x, gi, gj);
        }
        ev[tid] = s;
    }
    __syncthreads();

    if (tid == 0) {
        float bv1 = -FLT_MAX, bv2 = -FLT_MAX;
        int bi1 = -1;
        #pragma unroll
        for (int q = 0; q < NCAND; q++) {
            float v = ev[q];
            if (v > bv1) { bv2 = bv1; bv1 = v; bi1 = eidx[q]; }
            else if (v > bv2) { bv2 = v; }
        }
        g_V1f = bv1; g_V2f = bv2; g_I1 = bi1;
    }
}

// ---------------------------------------------------------------------------
// Kernel 3: sim_self in round-0 fp32 arithmetic + ratio partial sums.
// ---------------------------------------------------------------------------
__global__ void __launch_bounds__(256)
simself_kernel(const float* __restrict__ x)
{
    __shared__ double ss[256];
    const int tid = threadIdx.x;
    const int p = blockIdx.x * 256 + tid;

    const float V1 = g_V1f, V2 = g_V2f;
    const int   I1 = g_I1;

    float s_self = dot_fp32_r0(x, p, p + 1);
    float oth = (I1 == p * N_TOT + (p + 1)) ? V2 : V1;
    ss[tid] = (double)(oth / s_self);
    __syncthreads();
    #pragma unroll
    for (int s = 128; s > 0; s >>= 1) {
        if (tid < s) ss[tid] += ss[tid + s];
        __syncthreads();
    }
    if (tid == 0) g_part[blockIdx.x] = ss[0];
}

// ---------------------------------------------------------------------------
// Kernel 4: final sum (16 partials)
// ---------------------------------------------------------------------------
__global__ void __launch_bounds__(32)
final_kernel(float* __restrict__ out)
{
    const int tid = threadIdx.x;
    double v = (tid < 16) ? g_part[tid] : 0.0;
    #pragma unroll
    for (int off = 16; off > 0; off >>= 1)
        v += __shfl_down_sync(0xffffffff, v, off);
    if (tid == 0) out[0] = (float)(v / (double)P_CNT);
}

// ---------------------------------------------------------------------------
extern "C" void kernel_launch(void* const* d_in, const int* in_sizes, int n_in,
                              void* d_out, int out_size)
{
    const float* x = (const float*)d_in[0];
    float* out     = (float*)d_out;

    const int smem_bytes = 2 * TILE2 * TILE2 * (int)sizeof(float);  // 128 KB
    cudaFuncSetAttribute(gram_exact_kernel,
                         cudaFuncAttributeMaxDynamicSharedMemorySize, smem_bytes);

    gram_exact_kernel<<<NBLK2, 256, smem_bytes>>>(x);
    candidate_kernel<<<1, 256>>>(x);
    simself_kernel<<<16, 256>>>(x);
    final_kernel<<<1, 32>>>(out);
}

// round 15
// speedup vs baseline: 2.8712x; 1.7687x over previous
#include <cuda_runtime.h>
#include <cuda_bf16.h>
#include <float.h>
#include <math.h>
#include <cstdint>

// ---------------------------------------------------------------------------
// Problem constants: x is [8192, 128] fp32, n_images = 2.
// ---------------------------------------------------------------------------
#define N_TOT   8192
#define DIM     128
#define P_CNT   4096
#define TILE2   128
#define NT2     (N_TOT / TILE2)             // 64
#define NBLK2   (NT2 * (NT2 + 1) / 2)       // 2080 upper-tri 128x128 tiles
#define NCAND   8

// ---------------------------------------------------------------------------
// Device scratch (allocation-free)
// ---------------------------------------------------------------------------
__device__ float  g_bv1[NBLK2];
__device__ int    g_bi1[NBLK2];
__device__ float  g_bv2[NBLK2];
__device__ int    g_bi2[NBLK2];
__device__ float  g_V1f, g_V2f;
__device__ int    g_I1;
__device__ double g_part[16];

// ---------------------------------------------------------------------------
// Helpers
// ---------------------------------------------------------------------------
__device__ __forceinline__ uint32_t smem_u32(const void* p) {
    uint32_t a;
    asm("{ .reg .u64 t; cvta.to.shared.u64 t, %1; cvt.u32.u64 %0, t; }" : "=r"(a) : "l"(p));
    return a;
}
#define SWZ128(b) ((b) ^ (((b) >> 3) & 0x70))

__device__ __forceinline__ void ldsm_x4(uint32_t& r0, uint32_t& r1, uint32_t& r2, uint32_t& r3,
                                        uint32_t addr) {
    asm volatile("ldmatrix.sync.aligned.m8n8.x4.shared.b16 {%0,%1,%2,%3}, [%4];"
        : "=r"(r0), "=r"(r1), "=r"(r2), "=r"(r3) : "r"(addr));
}
__device__ __forceinline__ void mma16816(float* c,
                                         uint32_t a0, uint32_t a1, uint32_t a2, uint32_t a3,
                                         uint32_t b0, uint32_t b1) {
    asm volatile("mma.sync.aligned.m16n8k16.row.col.f32.bf16.bf16.f32 "
        "{%0,%1,%2,%3}, {%4,%5,%6,%7}, {%8,%9}, {%0,%1,%2,%3};"
        : "+f"(c[0]), "+f"(c[1]), "+f"(c[2]), "+f"(c[3])
        : "r"(a0), "r"(a1), "r"(a2), "r"(a3), "r"(b0), "r"(b1));
}

// Round-0-style fp32 dot: float4 lanes, 4 fmaf accumulators, (a0+a1)+(a2+a3).
__device__ __forceinline__ float dot_fp32_r0(const float* __restrict__ x, int gi, int gj)
{
    const float4* xa = (const float4*)(x + (size_t)gi * DIM);
    const float4* xb = (const float4*)(x + (size_t)gj * DIM);
    float a0 = 0.f, a1 = 0.f, a2 = 0.f, a3 = 0.f;
    #pragma unroll
    for (int c = 0; c < DIM / 4; c++) {
        float4 a = xa[c];
        float4 b = xb[c];
        a0 = fmaf(a.x, b.x, a0);
        a1 = fmaf(a.y, b.y, a1);
        a2 = fmaf(a.z, b.z, a2);
        a3 = fmaf(a.w, b.w, a3);
    }
    return (a0 + a1) + (a2 + a3);
}

// ---------------------------------------------------------------------------
// Kernel 1: 128x128 G tile via warp-level mma.sync (bf16 hi/lo split done
// IN-KERNEL from fp32 x; no device-global intermediates) + per-block top-2.
//
// SMEM: 8 half-buffers of 128 rows x 64 bf16 (128 B/row, SW128 XOR swizzle):
//   {A,B} x {hi,lo} x {K-half0, K-half1}, 16 KB each = 128 KB.
// Warp w (of 8): C sub-tile rows (w&3)*32, cols (w>>2)*64; 2x8 m16n8 frags.
// Passes: (Ahi,Bhi), (Ahi,Blo), (Alo,Bhi).
// ---------------------------------------------------------------------------
#define TB      16384
#define SM_AH0  0
#define SM_AL0  (2 * TB)
#define SM_BH0  (4 * TB)
#define SM_BL0  (6 * TB)
#define SM_TOT  (8 * TB)   // 131072 bytes

// Load a 128-row fp32 panel, split each 8-float chunk into bf16 hi + lo, and
// store both into their swizzled SMEM half-buffers.
__device__ __forceinline__ void load_split_panel(char* smem, int off_hi, int off_lo,
                                                 const float* __restrict__ src,
                                                 int rowbase, int tid)
{
    // 128 rows x 16 chunks (8 floats each); chunks 0-7 -> K-half0, 8-15 -> K-half1.
    #pragma unroll
    for (int it = 0; it < 8; it++) {
        int idx = tid + it * 256;
        int row = idx >> 4;
        int ch  = idx & 15;
        int half = ch >> 3;
        int wcol = (ch & 7) * 8;   // bf16 column within the 64-wide K-half
        const float* p = src + (size_t)(rowbase + row) * DIM + half * 64 + wcol;
        float4 f0 = *(const float4*)p;
        float4 f1 = *(const float4*)(p + 4);
        float f[8] = { f0.x, f0.y, f0.z, f0.w, f1.x, f1.y, f1.z, f1.w };
        __nv_bfloat16 h[8], l[8];
        #pragma unroll
        for (int q = 0; q < 8; q++) {
            h[q] = __float2bfloat16(f[q]);
            l[q] = __float2bfloat16(f[q] - __bfloat162float(h[q]));
        }
        uint32_t byte_off = (uint32_t)row * 128 + (uint32_t)wcol * 2;
        uint32_t sw = SWZ128(byte_off);   // 16B-aligned, swizzle preserves alignment
        *(uint4*)(smem + off_hi + half * TB + sw) = *(uint4*)h;
        *(uint4*)(smem + off_lo + half * TB + sw) = *(uint4*)l;
    }
}

__global__ void __launch_bounds__(256, 1)
gram_top2_kernel(const float* __restrict__ x)
{
    extern __shared__ char smem[];
    const uint32_t smem_u = smem_u32(smem);
    const int tid = threadIdx.x;
    const int wid = tid >> 5;
    const int lane = tid & 31;

    int b = blockIdx.x;
    int ti = 0;
    while (b >= NT2 - ti) { b -= NT2 - ti; ti++; }
    const int tj = ti + b;
    const int rowbase = ti * TILE2;
    const int colbase = tj * TILE2;

    load_split_panel(smem, SM_AH0, SM_AL0, x, rowbase, tid);
    load_split_panel(smem, SM_BH0, SM_BL0, x, colbase, tid);
    __syncthreads();

    const int wm = wid & 3;        // row block (32 rows)
    const int wn = wid >> 2;       // col block (64 cols)

    // ldmatrix lane geometry (audited against PTX ISA fragment layouts).
    // A x4 (m16k16): lanes 0-15 rows 0-15 k-low16B, lanes 16-31 same rows k-high.
    const int a_row = wm * 32 + (lane & 15);
    const uint32_t a_klo = ((uint32_t)(lane >> 4)) * 16;
    const uint32_t a_xor = ((uint32_t)(a_row & 7)) << 4;
    const uint32_t a_base0 = smem_u + (uint32_t)a_row * 128;        // mi=0
    const uint32_t a_base1 = a_base0 + 16 * 128;                    // mi=1
    // B x4 (two n8k16 frags): lanes 0-7 n0-7 klo, 8-15 n0-7 khi,
    //                         16-23 n8-15 klo, 24-31 n8-15 khi.
    const int b_row = wn * 64 + (lane & 7) + ((lane >> 4) << 3);
    const uint32_t b_klo = ((uint32_t)((lane >> 3) & 1)) * 16;
    const uint32_t b_xor = ((uint32_t)(b_row & 7)) << 4;
    uint32_t b_base[4];
    #pragma unroll
    for (int np = 0; np < 4; np++)
        b_base[np] = smem_u + (uint32_t)(b_row + np * 16) * 128;

    float c[2][8][4];
    #pragma unroll
    for (int mi = 0; mi < 2; mi++)
        #pragma unroll
        for (int ni = 0; ni < 8; ni++)
            #pragma unroll
            for (int q = 0; q < 4; q++) c[mi][ni][q] = 0.f;

    #pragma unroll
    for (int pass = 0; pass < 3; pass++) {
        const uint32_t abuf = (pass == 2) ? SM_AL0 : SM_AH0;
        const uint32_t bbuf = (pass == 1) ? SM_BL0 : SM_BH0;
        #pragma unroll
        for (int ks = 0; ks < 8; ks++) {
            const uint32_t hoff = (ks < 4) ? 0u : (uint32_t)TB;
            const uint32_t kb   = (uint32_t)(ks & 3) * 32;
            uint32_t a0[4], a1[4];
            ldsm_x4(a0[0], a0[1], a0[2], a0[3], a_base0 + abuf + hoff + ((kb + a_klo) ^ a_xor));
            ldsm_x4(a1[0], a1[1], a1[2], a1[3], a_base1 + abuf + hoff + ((kb + a_klo) ^ a_xor));
            #pragma unroll
            for (int np = 0; np < 4; np++) {
                uint32_t b0, b1, b2, b3;
                ldsm_x4(b0, b1, b2, b3, b_base[np] + bbuf + hoff + ((kb + b_klo) ^ b_xor));
                mma16816(c[0][2 * np + 0], a0[0], a0[1], a0[2], a0[3], b0, b1);
                mma16816(c[1][2 * np + 0], a1[0], a1[1], a1[2], a1[3], b0, b1);
                mma16816(c[0][2 * np + 1], a0[0], a0[1], a0[2], a0[3], b2, b3);
                mma16816(c[1][2 * np + 1], a1[0], a1[1], a1[2], a1[3], b2, b3);
            }
        }
    }

    // Per-thread top-2 over this thread's 64 C values (strict upper triangle).
    const int g = lane >> 2;
    const int t = lane & 3;
    float v1 = -FLT_MAX, v2 = -FLT_MAX;
    int   i1 = -1,       i2 = -1;
    #pragma unroll
    for (int mi = 0; mi < 2; mi++) {
        #pragma unroll
        for (int ni = 0; ni < 8; ni++) {
            #pragma unroll
            for (int q = 0; q < 4; q++) {
                int grow = rowbase + wm * 32 + 16 * mi + g + ((q >> 1) << 3);
                int gcol = colbase + wn * 64 + 8 * ni + 2 * t + (q & 1);
                if (gcol > grow) {
                    float val = c[mi][ni][q];
                    if (val > v1) { v2 = v1; i2 = i1; v1 = val; i1 = grow * N_TOT + gcol; }
                    else if (val > v2) { v2 = val; i2 = grow * N_TOT + gcol; }
                }
            }
        }
    }

    // Block reduce (v1,i1,v2,i2); reuse tile SMEM.
    __syncthreads();
    float* rv1 = (float*)smem;
    float* rv2 = rv1 + 256;
    int*   ri1 = (int*)(rv2 + 256);
    int*   ri2 = ri1 + 256;
    rv1[tid] = v1; rv2[tid] = v2; ri1[tid] = i1; ri2[tid] = i2;
    __syncthreads();
    #pragma unroll
    for (int s = 128; s > 0; s >>= 1) {
        if (tid < s) {
            float av1 = rv1[tid], av2 = rv2[tid];
            int   ai1 = ri1[tid];
            float bv1 = rv1[tid + s], bv2 = rv2[tid + s];
            int   bi1 = ri1[tid + s], bi2 = ri2[tid + s];
            if (bv1 > av1) {
                rv1[tid] = bv1; ri1[tid] = bi1;
                if (av1 > bv2) { rv2[tid] = av1; ri2[tid] = ai1; }
                else           { rv2[tid] = bv2; ri2[tid] = bi2; }
            } else {
                if (bv1 > av2) { rv2[tid] = bv1; ri2[tid] = bi1; }
            }
        }
        __syncthreads();
    }
    if (tid == 0) {
        g_bv1[blockIdx.x] = rv1[0]; g_bi1[blockIdx.x] = ri1[0];
        g_bv2[blockIdx.x] = rv2[0]; g_bi2[blockIdx.x] = ri2[0];
    }
}

// ---------------------------------------------------------------------------
// Kernel 2: merge per-block candidates -> top-NCAND, recompute those pair-dots
// with round-0 fp32 ordering, select top-2 -> g_V1f/g_V2f/g_I1.
// (Machinery proven correct in round 11.)
// ---------------------------------------------------------------------------
__global__ void __launch_bounds__(256)
candidate_kernel(const float* __restrict__ x)
{
    __shared__ float cv[1024];
    __shared__ int   ci[1024];
    __shared__ float cv2[128];
    __shared__ int   ci2[128];
    __shared__ float ev[NCAND];
    __shared__ int   eidx[NCAND];

    const int tid = threadIdx.x;

    // Stage 1: per-thread top-4 over 2*NBLK2 entries.
    float lv[4] = { -FLT_MAX, -FLT_MAX, -FLT_MAX, -FLT_MAX };
    int   li[4] = { -1, -1, -1, -1 };
    for (int e = tid; e < 2 * NBLK2; e += 256) {
        int bb = e >> 1;
        float v = (e & 1) ? g_bv2[bb] : g_bv1[bb];
        int   i = (e & 1) ? g_bi2[bb] : g_bi1[bb];
        if (v > lv[3]) {
            int q = 3;
            while (q > 0 && v > lv[q - 1]) { lv[q] = lv[q - 1]; li[q] = li[q - 1]; q--; }
            lv[q] = v; li[q] = i;
        }
    }
    #pragma unroll
    for (int q = 0; q < 4; q++) { cv[tid * 4 + q] = lv[q]; ci[tid * 4 + q] = li[q]; }
    __syncthreads();

    // Stage 2: 32 threads each merge 8 lists -> top-4 into cv2/ci2.
    if (tid < 32) {
        float mv[4] = { -FLT_MAX, -FLT_MAX, -FLT_MAX, -FLT_MAX };
        int   mi[4] = { -1, -1, -1, -1 };
        for (int e = 0; e < 32; e++) {
            float v = cv[tid * 32 + e];
            int   i = ci[tid * 32 + e];
            if (v > mv[3]) {
                int q = 3;
                while (q > 0 && v > mv[q - 1]) { mv[q] = mv[q - 1]; mi[q] = mi[q - 1]; q--; }
                mv[q] = v; mi[q] = i;
            }
        }
        #pragma unroll
        for (int q = 0; q < 4; q++) { cv2[tid * 4 + q] = mv[q]; ci2[tid * 4 + q] = mi[q]; }
    }
    __syncthreads();

    // Stage 3: thread 0 merges 128 entries -> final top-NCAND candidates.
    if (tid == 0) {
        float fv[NCAND];
        int   fi[NCAND];
        #pragma unroll
        for (int q = 0; q < NCAND; q++) { fv[q] = -FLT_MAX; fi[q] = -1; }
        for (int e = 0; e < 128; e++) {
            float v = cv2[e];
            int   i = ci2[e];
            if (v > fv[NCAND - 1]) {
                int q = NCAND - 1;
                while (q > 0 && v > fv[q - 1]) { fv[q] = fv[q - 1]; fi[q] = fi[q - 1]; q--; }
                fv[q] = v; fi[q] = i;
            }
        }
        #pragma unroll
        for (int q = 0; q < NCAND; q++) eidx[q] = fi[q];
    }
    __syncthreads();

    // Recompute candidate pair-dots with round-0 fp32 ordering.
    if (tid < NCAND) {
        int idx = eidx[tid];
        float s = -FLT_MAX;
        if (idx >= 0) {
            int gi = idx / N_TOT, gj = idx % N_TOT;
            s = dot_fp32_r0(x, gi, gj);
        }
        ev[tid] = s;
    }
    __syncthreads();

    if (tid == 0) {
        float bv1 = -FLT_MAX, bv2 = -FLT_MAX;
        int bi1 = -1;
        #pragma unroll
        for (int q = 0; q < NCAND; q++) {
            float v = ev[q];
            if (v > bv1) { bv2 = bv1; bv1 = v; bi1 = eidx[q]; }
            else if (v > bv2) { bv2 = v; }
        }
        g_V1f = bv1; g_V2f = bv2; g_I1 = bi1;
    }
}

// ---------------------------------------------------------------------------
// Kernel 3: sim_self in round-0 fp32 arithmetic + ratio partial sums.
// ---------------------------------------------------------------------------
__global__ void __launch_bounds__(256)
simself_kernel(const float* __restrict__ x)
{
    __shared__ double ss[256];
    const int tid = threadIdx.x;
    const int p = blockIdx.x * 256 + tid;

    const float V1 = g_V1f, V2 = g_V2f;
    const int   I1 = g_I1;

    float s_self = dot_fp32_r0(x, p, p + 1);
    float oth = (I1 == p * N_TOT + (p + 1)) ? V2 : V1;
    ss[tid] = (double)(oth / s_self);
    __syncthreads();
    #pragma unroll
    for (int s = 128; s > 0; s >>= 1) {
        if (tid < s) ss[tid] += ss[tid + s];
        __syncthreads();
    }
    if (tid == 0) g_part[blockIdx.x] = ss[0];
}

// ---------------------------------------------------------------------------
// Kernel 4: final sum (16 partials)
// ---------------------------------------------------------------------------
__global__ void __launch_bounds__(32)
final_kernel(float* __restrict__ out)
{
    const int tid = threadIdx.x;
    double v = (tid < 16) ? g_part[tid] : 0.0;
    #pragma unroll
    for (int off = 16; off > 0; off >>= 1)
        v += __shfl_down_sync(0xffffffff, v, off);
    if (tid == 0) out[0] = (float)(v / (double)P_CNT);
}

// ---------------------------------------------------------------------------
extern "C" void kernel_launch(void* const* d_in, const int* in_sizes, int n_in,
                              void* d_out, int out_size)
{
    const float* x = (const float*)d_in[0];
    float* out     = (float*)d_out;

    cudaFuncSetAttribute(gram_top2_kernel,
                         cudaFuncAttributeMaxDynamicSharedMemorySize, SM_TOT);

    gram_top2_kernel<<<NBLK2, 256, SM_TOT>>>(x);
    candidate_kernel<<<1, 256>>>(x);
    simself_kernel<<<16, 256>>>(x);
    final_kernel<<<1, 32>>>(out);
}

// round 16
// speedup vs baseline: 5.1741x; 1.8021x over previous
#include <cuda_runtime.h>
#include <cuda_bf16.h>
#include <float.h>
#include <math.h>
#include <cstdint>

// ---------------------------------------------------------------------------
// Problem constants: x is [8192, 128] fp32, n_images = 2.
// ---------------------------------------------------------------------------
#define N_TOT   8192
#define DIM     128
#define P_CNT   4096
#define TILE2   128
#define NT2     (N_TOT / TILE2)             // 64
#define NBLK2   (NT2 * (NT2 + 1) / 2)       // 2080 upper-tri 128x128 tiles
#define NCAND   8

// ---------------------------------------------------------------------------
// Device scratch (allocation-free)
// ---------------------------------------------------------------------------
__device__ float  g_bv1[NBLK2];
__device__ int    g_bi1[NBLK2];
__device__ float  g_bv2[NBLK2];
__device__ int    g_bi2[NBLK2];
__device__ float  g_V1f, g_V2f;
__device__ int    g_I1;
__device__ double g_part[16];

// ---------------------------------------------------------------------------
// Helpers
// ---------------------------------------------------------------------------
__device__ __forceinline__ uint32_t smem_u32(const void* p) {
    uint32_t a;
    asm("{ .reg .u64 t; cvta.to.shared.u64 t, %1; cvt.u32.u64 %0, t; }" : "=r"(a) : "l"(p));
    return a;
}
#define SWZ128(b) ((b) ^ (((b) >> 3) & 0x70))

__device__ __forceinline__ void ldsm_x4(uint32_t& r0, uint32_t& r1, uint32_t& r2, uint32_t& r3,
                                        uint32_t addr) {
    asm volatile("ldmatrix.sync.aligned.m8n8.x4.shared.b16 {%0,%1,%2,%3}, [%4];"
        : "=r"(r0), "=r"(r1), "=r"(r2), "=r"(r3) : "r"(addr));
}
__device__ __forceinline__ void mma16816(float* c,
                                         uint32_t a0, uint32_t a1, uint32_t a2, uint32_t a3,
                                         uint32_t b0, uint32_t b1) {
    asm volatile("mma.sync.aligned.m16n8k16.row.col.f32.bf16.bf16.f32 "
        "{%0,%1,%2,%3}, {%4,%5,%6,%7}, {%8,%9}, {%0,%1,%2,%3};"
        : "+f"(c[0]), "+f"(c[1]), "+f"(c[2]), "+f"(c[3])
        : "r"(a0), "r"(a1), "r"(a2), "r"(a3), "r"(b0), "r"(b1));
}

// Round-0-style fp32 dot: float4 lanes, 4 fmaf accumulators, (a0+a1)+(a2+a3).
__device__ __forceinline__ float dot_fp32_r0(const float* __restrict__ x, int gi, int gj)
{
    const float4* xa = (const float4*)(x + (size_t)gi * DIM);
    const float4* xb = (const float4*)(x + (size_t)gj * DIM);
    float a0 = 0.f, a1 = 0.f, a2 = 0.f, a3 = 0.f;
    #pragma unroll
    for (int c = 0; c < DIM / 4; c++) {
        float4 a = xa[c];
        float4 b = xb[c];
        a0 = fmaf(a.x, b.x, a0);
        a1 = fmaf(a.y, b.y, a1);
        a2 = fmaf(a.z, b.z, a2);
        a3 = fmaf(a.w, b.w, a3);
    }
    return (a0 + a1) + (a2 + a3);
}

// ---------------------------------------------------------------------------
// Kernel 1: 128x128 G tile via warp-level mma.sync, SINGLE-PASS plain bf16
// (selection-grade precision; candidates re-verified exactly downstream).
//
// SMEM: {A,B} panels, each 128 rows x 128 K bf16 as two 16 KB K-half buffers
// (128 B/row, SW128 XOR swizzle) -> 64 KB total -> 2 CTAs/SM.
// Warp w (of 8): C sub-tile rows (w&3)*32, cols (w>>2)*64; 2x8 m16n8 frags.
// ---------------------------------------------------------------------------
#define TB      16384
#define SM_A0   0
#define SM_B0   (2 * TB)
#define SM_TOT  (4 * TB)   // 65536 bytes

// Load a 128-row fp32 panel, convert to bf16, store swizzled.
__device__ __forceinline__ void load_bf16_panel(char* smem, int off,
                                                const float* __restrict__ src,
                                                int rowbase, int tid)
{
    // 128 rows x 16 chunks (8 floats each); chunks 0-7 -> K-half0, 8-15 -> K-half1.
    #pragma unroll
    for (int it = 0; it < 8; it++) {
        int idx = tid + it * 256;
        int row = idx >> 4;
        int ch  = idx & 15;
        int half = ch >> 3;
        int wcol = (ch & 7) * 8;   // bf16 column within the 64-wide K-half
        const float* p = src + (size_t)(rowbase + row) * DIM + half * 64 + wcol;
        float4 f0 = *(const float4*)p;
        float4 f1 = *(const float4*)(p + 4);
        float f[8] = { f0.x, f0.y, f0.z, f0.w, f1.x, f1.y, f1.z, f1.w };
        __nv_bfloat16 h[8];
        #pragma unroll
        for (int q = 0; q < 8; q++) h[q] = __float2bfloat16(f[q]);
        uint32_t byte_off = (uint32_t)row * 128 + (uint32_t)wcol * 2;
        uint32_t sw = SWZ128(byte_off);   // 16B-aligned, swizzle preserves alignment
        *(uint4*)(smem + off + half * TB + sw) = *(uint4*)h;
    }
}

__global__ void __launch_bounds__(256, 2)
gram_top2_kernel(const float* __restrict__ x)
{
    extern __shared__ char smem[];
    const uint32_t smem_u = smem_u32(smem);
    const int tid = threadIdx.x;
    const int wid = tid >> 5;
    const int lane = tid & 31;

    int b = blockIdx.x;
    int ti = 0;
    while (b >= NT2 - ti) { b -= NT2 - ti; ti++; }
    const int tj = ti + b;
    const int rowbase = ti * TILE2;
    const int colbase = tj * TILE2;

    load_bf16_panel(smem, SM_A0, x, rowbase, tid);
    load_bf16_panel(smem, SM_B0, x, colbase, tid);
    __syncthreads();

    const int wm = wid & 3;        // row block (32 rows)
    const int wn = wid >> 2;       // col block (64 cols)

    // ldmatrix lane geometry (validated in round 15).
    const int a_row = wm * 32 + (lane & 15);
    const uint32_t a_klo = ((uint32_t)(lane >> 4)) * 16;
    const uint32_t a_xor = ((uint32_t)(a_row & 7)) << 4;
    const uint32_t a_base0 = smem_u + SM_A0 + (uint32_t)a_row * 128;   // mi=0
    const uint32_t a_base1 = a_base0 + 16 * 128;                       // mi=1
    const int b_row = wn * 64 + (lane & 7) + ((lane >> 4) << 3);
    const uint32_t b_klo = ((uint32_t)((lane >> 3) & 1)) * 16;
    const uint32_t b_xor = ((uint32_t)(b_row & 7)) << 4;
    uint32_t b_base[4];
    #pragma unroll
    for (int np = 0; np < 4; np++)
        b_base[np] = smem_u + SM_B0 + (uint32_t)(b_row + np * 16) * 128;

    float c[2][8][4];
    #pragma unroll
    for (int mi = 0; mi < 2; mi++)
        #pragma unroll
        for (int ni = 0; ni < 8; ni++)
            #pragma unroll
            for (int q = 0; q < 4; q++) c[mi][ni][q] = 0.f;

    #pragma unroll
    for (int ks = 0; ks < 8; ks++) {
        const uint32_t hoff = (ks < 4) ? 0u : (uint32_t)TB;
        const uint32_t kb   = (uint32_t)(ks & 3) * 32;
        uint32_t a0[4], a1[4];
        ldsm_x4(a0[0], a0[1], a0[2], a0[3], a_base0 + hoff + ((kb + a_klo) ^ a_xor));
        ldsm_x4(a1[0], a1[1], a1[2], a1[3], a_base1 + hoff + ((kb + a_klo) ^ a_xor));
        #pragma unroll
        for (int np = 0; np < 4; np++) {
            uint32_t b0, b1, b2, b3;
            ldsm_x4(b0, b1, b2, b3, b_base[np] + hoff + ((kb + b_klo) ^ b_xor));
            mma16816(c[0][2 * np + 0], a0[0], a0[1], a0[2], a0[3], b0, b1);
            mma16816(c[1][2 * np + 0], a1[0], a1[1], a1[2], a1[3], b0, b1);
            mma16816(c[0][2 * np + 1], a0[0], a0[1], a0[2], a0[3], b2, b3);
            mma16816(c[1][2 * np + 1], a1[0], a1[1], a1[2], a1[3], b2, b3);
        }
    }

    // Per-thread top-2 over this thread's 64 C values (strict upper triangle).
    const int g = lane >> 2;
    const int t = lane & 3;
    float v1 = -FLT_MAX, v2 = -FLT_MAX;
    int   i1 = -1,       i2 = -1;
    #pragma unroll
    for (int mi = 0; mi < 2; mi++) {
        #pragma unroll
        for (int ni = 0; ni < 8; ni++) {
            #pragma unroll
            for (int q = 0; q < 4; q++) {
                int grow = rowbase + wm * 32 + 16 * mi + g + ((q >> 1) << 3);
                int gcol = colbase + wn * 64 + 8 * ni + 2 * t + (q & 1);
                if (gcol > grow) {
                    float val = c[mi][ni][q];
                    if (val > v1) { v2 = v1; i2 = i1; v1 = val; i1 = grow * N_TOT + gcol; }
                    else if (val > v2) { v2 = val; i2 = grow * N_TOT + gcol; }
                }
            }
        }
    }

    // Block reduce (v1,i1,v2,i2); reuse tile SMEM.
    __syncthreads();
    float* rv1 = (float*)smem;
    float* rv2 = rv1 + 256;
    int*   ri1 = (int*)(rv2 + 256);
    int*   ri2 = ri1 + 256;
    rv1[tid] = v1; rv2[tid] = v2; ri1[tid] = i1; ri2[tid] = i2;
    __syncthreads();
    #pragma unroll
    for (int s = 128; s > 0; s >>= 1) {
        if (tid < s) {
            float av1 = rv1[tid], av2 = rv2[tid];
            int   ai1 = ri1[tid];
            float bv1 = rv1[tid + s], bv2 = rv2[tid + s];
            int   bi1 = ri1[tid + s], bi2 = ri2[tid + s];
            if (bv1 > av1) {
                rv1[tid] = bv1; ri1[tid] = bi1;
                if (av1 > bv2) { rv2[tid] = av1; ri2[tid] = ai1; }
                else           { rv2[tid] = bv2; ri2[tid] = bi2; }
            } else {
                if (bv1 > av2) { rv2[tid] = bv1; ri2[tid] = bi1; }
            }
        }
        __syncthreads();
    }
    if (tid == 0) {
        g_bv1[blockIdx.x] = rv1[0]; g_bi1[blockIdx.x] = ri1[0];
        g_bv2[blockIdx.x] = rv2[0]; g_bi2[blockIdx.x] = ri2[0];
    }
}

// ---------------------------------------------------------------------------
// Kernel 2: merge per-block candidates -> top-NCAND, recompute those pair-dots
// with round-0 fp32 ordering, select top-2 -> g_V1f/g_V2f/g_I1.
// ---------------------------------------------------------------------------
__global__ void __launch_bounds__(256)
candidate_kernel(const float* __restrict__ x)
{
    __shared__ float cv[1024];
    __shared__ int   ci[1024];
    __shared__ float cv2[128];
    __shared__ int   ci2[128];
    __shared__ float ev[NCAND];
    __shared__ int   eidx[NCAND];

    const int tid = threadIdx.x;

    // Stage 1: per-thread top-4 over 2*NBLK2 entries.
    float lv[4] = { -FLT_MAX, -FLT_MAX, -FLT_MAX, -FLT_MAX };
    int   li[4] = { -1, -1, -1, -1 };
    for (int e = tid; e < 2 * NBLK2; e += 256) {
        int bb = e >> 1;
        float v = (e & 1) ? g_bv2[bb] : g_bv1[bb];
        int   i = (e & 1) ? g_bi2[bb] : g_bi1[bb];
        if (v > lv[3]) {
            int q = 3;
            while (q > 0 && v > lv[q - 1]) { lv[q] = lv[q - 1]; li[q] = li[q - 1]; q--; }
            lv[q] = v; li[q] = i;
        }
    }
    #pragma unroll
    for (int q = 0; q < 4; q++) { cv[tid * 4 + q] = lv[q]; ci[tid * 4 + q] = li[q]; }
    __syncthreads();

    // Stage 2: 32 threads each merge 8 lists -> top-4 into cv2/ci2.
    if (tid < 32) {
        float mv[4] = { -FLT_MAX, -FLT_MAX, -FLT_MAX, -FLT_MAX };
        int   mi[4] = { -1, -1, -1, -1 };
        for (int e = 0; e < 32; e++) {
            float v = cv[tid * 32 + e];
            int   i = ci[tid * 32 + e];
            if (v > mv[3]) {
                int q = 3;
                while (q > 0 && v > mv[q - 1]) { mv[q] = mv[q - 1]; mi[q] = mi[q - 1]; q--; }
                mv[q] = v; mi[q] = i;
            }
        }
        #pragma unroll
        for (int q = 0; q < 4; q++) { cv2[tid * 4 + q] = mv[q]; ci2[tid * 4 + q] = mi[q]; }
    }
    __syncthreads();

    // Stage 3: thread 0 merges 128 entries -> final top-NCAND candidates.
    if (tid == 0) {
        float fv[NCAND];
        int   fi[NCAND];
        #pragma unroll
        for (int q = 0; q < NCAND; q++) { fv[q] = -FLT_MAX; fi[q] = -1; }
        for (int e = 0; e < 128; e++) {
            float v = cv2[e];
            int   i = ci2[e];
            if (v > fv[NCAND - 1]) {
                int q = NCAND - 1;
                while (q > 0 && v > fv[q - 1]) { fv[q] = fv[q - 1]; fi[q] = fi[q - 1]; q--; }
                fv[q] = v; fi[q] = i;
            }
        }
        #pragma unroll
        for (int q = 0; q < NCAND; q++) eidx[q] = fi[q];
    }
    __syncthreads();

    // Recompute candidate pair-dots with round-0 fp32 ordering.
    if (tid < NCAND) {
        int idx = eidx[tid];
        float s = -FLT_MAX;
        if (idx >= 0) {
            int gi = idx / N_TOT, gj = idx % N_TOT;
            s = dot_fp32_r0(x, gi, gj);
        }
        ev[tid] = s;
    }
    __syncthreads();

    if (tid == 0) {
        float bv1 = -FLT_MAX, bv2 = -FLT_MAX;
        int bi1 = -1;
        #pragma unroll
        for (int q = 0; q < NCAND; q++) {
            float v = ev[q];
            if (v > bv1) { bv2 = bv1; bv1 = v; bi1 = eidx[q]; }
            else if (v > bv2) { bv2 = v; }
        }
        g_V1f = bv1; g_V2f = bv2; g_I1 = bi1;
    }
}

// ---------------------------------------------------------------------------
// Kernel 3: sim_self in round-0 fp32 arithmetic + ratio partial sums.
// ---------------------------------------------------------------------------
__global__ void __launch_bounds__(256)
simself_kernel(const float* __restrict__ x)
{
    __shared__ double ss[256];
    const int tid = threadIdx.x;
    const int p = blockIdx.x * 256 + tid;

    const float V1 = g_V1f, V2 = g_V2f;
    const int   I1 = g_I1;

    float s_self = dot_fp32_r0(x, p, p + 1);
    float oth = (I1 == p * N_TOT + (p + 1)) ? V2 : V1;
    ss[tid] = (double)(oth / s_self);
    __syncthreads();
    #pragma unroll
    for (int s = 128; s > 0; s >>= 1) {
        if (tid < s) ss[tid] += ss[tid + s];
        __syncthreads();
    }
    if (tid == 0) g_part[blockIdx.x] = ss[0];
}

// ---------------------------------------------------------------------------
// Kernel 4: final sum (16 partials)
// ---------------------------------------------------------------------------
__global__ void __launch_bounds__(32)
final_kernel(float* __restrict__ out)
{
    const int tid = threadIdx.x;
    double v = (tid < 16) ? g_part[tid] : 0.0;
    #pragma unroll
    for (int off = 16; off > 0; off >>= 1)
        v += __shfl_down_sync(0xffffffff, v, off);
    if (tid == 0) out[0] = (float)(v / (double)P_CNT);
}

// ---------------------------------------------------------------------------
extern "C" void kernel_launch(void* const* d_in, const int* in_sizes, int n_in,
                              void* d_out, int out_size)
{
    const float* x = (const float*)d_in[0];
    float* out     = (float*)d_out;

    cudaFuncSetAttribute(gram_top2_kernel,
                         cudaFuncAttributeMaxDynamicSharedMemorySize, SM_TOT);

    gram_top2_kernel<<<NBLK2, 256, SM_TOT>>>(x);
    candidate_kernel<<<1, 256>>>(x);
    simself_kernel<<<16, 256>>>(x);
    final_kernel<<<1, 32>>>(out);
}